// round 4
// baseline (speedup 1.0000x reference)
#include <cuda_runtime.h>
#include <cstdint>
#include <math.h>

// Problem constants
#define DD 768
#define RR 16
#define TT 8
#define M_ROWS 8192          // B*S = 32*256
#define NOUT 2304            // 3*D
#define KMID 144             // per-branch low-rank K (8*16 MoE + 16 LoRA)
#define ZC 288               // 2*KMID

// ---------------- static scratch (no allocations allowed) ----------------
__device__ __align__(16) float g_xt[M_ROWS * DD];     // x pre-rounded to tf32
__device__ __align__(16) float g_wt[NOUT * DD];       // qkv_w pre-rounded
__device__ __align__(16) float g_Acat[ZC * DD];       // concat A rows (tf32)
__device__ __align__(16) float g_Bqs[DD * KMID];      // scaled B_q^T-ish (tf32)
__device__ __align__(16) float g_Bvs[DD * KMID];
__device__ __align__(16) float g_z[M_ROWS * ZC];      // z = x @ Acat^T (tf32)
__device__ float g_normsq[32];                        // [Aq(8),Bq(8),Av(8),Bv(8)]
__device__ float g_scaleq[TT];
__device__ float g_scalev[TT];
__device__ float g_acur;

// ---------------- helpers ----------------
__device__ __forceinline__ float f2tf32(float x) {
    uint32_t u;
    asm("cvt.rna.tf32.f32 %0, %1;" : "=r"(u) : "f"(x));
    return __uint_as_float(u);
}

__device__ __forceinline__ void cp16(void* sdst, const void* gsrc) {
    unsigned s = (unsigned)__cvta_generic_to_shared(sdst);
    asm volatile("cp.async.cg.shared.global [%0], [%1], 16;\n" :: "r"(s), "l"(gsrc));
}

__device__ __forceinline__ void mma_tf32(float c[4], const uint32_t a[4], const uint32_t b[2]) {
    asm volatile(
        "mma.sync.aligned.m16n8k8.row.col.f32.tf32.tf32.f32 "
        "{%0,%1,%2,%3},{%4,%5,%6,%7},{%8,%9},{%0,%1,%2,%3};\n"
        : "+f"(c[0]), "+f"(c[1]), "+f"(c[2]), "+f"(c[3])
        : "r"(a[0]), "r"(a[1]), "r"(a[2]), "r"(a[3]),
          "r"(b[0]), "r"(b[1]));
}

// ---------------- prepass kernels ----------------
// 32 blocks: block b -> which=b>>3 in {Aq,Bq,Av,Bv}, task t=b&7. Sum of squares.
__global__ void norms_kernel(const float* __restrict__ Aq, const float* __restrict__ Bq,
                             const float* __restrict__ Av, const float* __restrict__ Bv) {
    __shared__ float red[256];
    int b = blockIdx.x, which = b >> 3, t = b & 7;
    const float* p = (which == 0) ? Aq : (which == 1) ? Bq : (which == 2) ? Av : Bv;
    p += t * (RR * DD);
    float s = 0.f;
    for (int i = threadIdx.x; i < RR * DD; i += 256) { float v = p[i]; s += v * v; }
    red[threadIdx.x] = s;
    __syncthreads();
    for (int o = 128; o > 0; o >>= 1) {
        if (threadIdx.x < o) red[threadIdx.x] += red[threadIdx.x + o];
        __syncthreads();
    }
    if (threadIdx.x == 0) g_normsq[b] = red[0];
}

__global__ void scales_kernel(const float* __restrict__ gate, const float* __restrict__ alpha) {
    if (threadIdx.x == 0) {
        float mx = gate[0];
        for (int t = 1; t < TT; t++) mx = fmaxf(mx, gate[t]);
        float e[TT], se = 0.f;
        for (int t = 0; t < TT; t++) { e[t] = expf(gate[t] - mx); se += e[t]; }
        for (int t = 0; t < TT; t++) {
            float beta = e[t] / se;
            g_scaleq[t] = beta / (sqrtf(g_normsq[t]) * sqrtf(g_normsq[8 + t]));
            g_scalev[t] = beta / (sqrtf(g_normsq[16 + t]) * sqrtf(g_normsq[24 + t]));
        }
        g_acur = alpha[TT];
    }
}

// Build Acat [288][768], Bqs/Bvs [768][144], all tf32-rounded, scales folded into B.
__global__ void build_kernel(const float* __restrict__ Aq, const float* __restrict__ laq,
                             const float* __restrict__ Av, const float* __restrict__ lav,
                             const float* __restrict__ Bq, const float* __restrict__ lbq,
                             const float* __restrict__ Bv, const float* __restrict__ lbv) {
    int i0 = blockIdx.x * blockDim.x + threadIdx.x;
    int stride = gridDim.x * blockDim.x;
    for (int i = i0; i < ZC * DD; i += stride) {
        int j = i / DD, d = i % DD;
        float v;
        if (j < 128)      v = Aq[i];                       // A_q flattened [128,768]
        else if (j < 144) v = laq[(j - 128) * DD + d];
        else if (j < 272) v = Av[(j - 144) * DD + d];
        else              v = lav[(j - 272) * DD + d];
        g_Acat[i] = f2tf32(v);
    }
    for (int i = i0; i < DD * KMID; i += stride) {
        int d = i / KMID, j = i % KMID;
        float vq, vv;
        if (j < 128) {
            int t = j >> 4, r = j & 15;
            vq = Bq[t * (DD * RR) + d * RR + r] * g_scaleq[t];
            vv = Bv[t * (DD * RR) + d * RR + r] * g_scalev[t];
        } else {
            vq = lbq[d * RR + (j - 128)] * g_acur;
            vv = lbv[d * RR + (j - 128)] * g_acur;
        }
        g_Bqs[i] = f2tf32(vq);
        g_Bvs[i] = f2tf32(vv);
    }
}

// tf32-round copy: which=0 -> g_xt, which=1 -> g_wt
__global__ void convert_kernel(const float4* __restrict__ src, int n4, int which) {
    float4* dst = (which == 0) ? (float4*)g_xt : (float4*)g_wt;
    int i = blockIdx.x * blockDim.x + threadIdx.x;
    int st = gridDim.x * blockDim.x;
    for (; i < n4; i += st) {
        float4 v = src[i];
        v.x = f2tf32(v.x); v.y = f2tf32(v.y); v.z = f2tf32(v.z); v.w = f2tf32(v.w);
        dst[i] = v;
    }
}

// ---------------- tf32 mma.sync GEMM ----------------
// MODE 0: z[8192,288] = xt @ Acat^T        (stores tf32-rounded, guard N=288)
// MODE 1: out[8192,2304] = xt @ wt^T + bias, plus fused low-rank delta:
//         n in [0,768):     += z[:, :144] @ Bqs^T
//         n in [1536,2304): += z[:,144:]  @ Bvs^T
template <int MODE>
__global__ __launch_bounds__(256, 2) void gemm_tf32(const float* __restrict__ bias,
                                                    float* __restrict__ Cout) {
    constexpr int BM = 128, BN = 128, BK = 16, BKP = 20;
    __shared__ float As[2][BM][BKP];
    __shared__ float Bs[2][BN][BKP];

    const int tid = threadIdx.x, lane = tid & 31, w = tid >> 5;
    const int g = lane >> 2, tg = lane & 3;
    const int wm = (w >> 2) * 64, wn = (w & 3) * 32;     // 2x4 warp grid, 64x32 tiles
    const int rowbase = blockIdx.y * BM, colbase = blockIdx.x * BN;

    const float* Ap1 = g_xt + (size_t)rowbase * DD;
    const float* Bp1;
    const float* Ap2 = nullptr;
    const float* Bp2 = nullptr;
    int KT2 = 0;
    float* C;
    int ldc;
    if constexpr (MODE == 0) {
        Bp1 = g_Acat + (size_t)colbase * DD;
        C = g_z; ldc = ZC;
    } else {
        Bp1 = g_wt + (size_t)colbase * DD;
        C = Cout; ldc = NOUT;
        if (colbase < DD) {
            KT2 = KMID / BK;
            Ap2 = g_z + (size_t)rowbase * ZC;
            Bp2 = g_Bqs + (size_t)colbase * KMID;
        } else if (colbase >= 2 * DD) {
            KT2 = KMID / BK;
            Ap2 = g_z + (size_t)rowbase * ZC + KMID;
            Bp2 = g_Bvs + (size_t)(colbase - 2 * DD) * KMID;
        }
    }
    constexpr int KT1 = DD / BK;  // 48
    const int KT = KT1 + KT2;

    float acc[4][4][4];
#pragma unroll
    for (int i = 0; i < 4; i++)
#pragma unroll
        for (int j = 0; j < 4; j++)
#pragma unroll
            for (int k = 0; k < 4; k++) acc[i][j][k] = 0.f;

    auto load_tile = [&](int stg, int kt) {
        const float* Ap; const float* Bp;
        int la, lb, kc;
        if (kt < KT1) { Ap = Ap1; la = DD;  Bp = Bp1; lb = DD;   kc = kt * BK; }
        else          { Ap = Ap2; la = ZC;  Bp = Bp2; lb = KMID; kc = (kt - KT1) * BK; }
#pragma unroll
        for (int i = 0; i < 2; i++) {
            int v = tid + i * 256, r = v >> 2, c = (v & 3) << 2;
            cp16(&As[stg][r][c], Ap + (size_t)r * la + kc + c);
        }
#pragma unroll
        for (int i = 0; i < 2; i++) {
            int v = tid + i * 256, r = v >> 2, c = (v & 3) << 2;
            bool ok = true;
            if constexpr (MODE == 0) ok = (colbase + r) < ZC;
            if (ok) cp16(&Bs[stg][r][c], Bp + (size_t)r * lb + kc + c);
            else *(float4*)&Bs[stg][r][c] = make_float4(0.f, 0.f, 0.f, 0.f);
        }
    };

    load_tile(0, 0);
    asm volatile("cp.async.commit_group;\n" ::);

    for (int kt = 0; kt < KT; kt++) {
        const int stg = kt & 1;
        asm volatile("cp.async.wait_group 0;\n" ::);
        __syncthreads();
        if (kt + 1 < KT) {
            load_tile((kt + 1) & 1, kt + 1);
            asm volatile("cp.async.commit_group;\n" ::);
        }
#pragma unroll
        for (int ks = 0; ks < 2; ks++) {
            const int kk = ks * 8;
            uint32_t afr[4][4], bfr[4][2];
#pragma unroll
            for (int fm = 0; fm < 4; fm++) {
                int r = wm + fm * 16 + g;
                afr[fm][0] = __float_as_uint(As[stg][r][kk + tg]);
                afr[fm][1] = __float_as_uint(As[stg][r + 8][kk + tg]);
                afr[fm][2] = __float_as_uint(As[stg][r][kk + tg + 4]);
                afr[fm][3] = __float_as_uint(As[stg][r + 8][kk + tg + 4]);
            }
#pragma unroll
            for (int fn = 0; fn < 4; fn++) {
                int n = wn + fn * 8 + g;
                bfr[fn][0] = __float_as_uint(Bs[stg][n][kk + tg]);
                bfr[fn][1] = __float_as_uint(Bs[stg][n][kk + tg + 4]);
            }
#pragma unroll
            for (int fm = 0; fm < 4; fm++)
#pragma unroll
                for (int fn = 0; fn < 4; fn++)
                    mma_tf32(acc[fm][fn], afr[fm], bfr[fn]);
        }
    }

    // epilogue
#pragma unroll
    for (int fm = 0; fm < 4; fm++) {
        int r0 = rowbase + wm + fm * 16 + g;
#pragma unroll
        for (int fn = 0; fn < 4; fn++) {
            int col = colbase + wn + fn * 8 + 2 * tg;
            float2 v0 = make_float2(acc[fm][fn][0], acc[fm][fn][1]);
            float2 v1 = make_float2(acc[fm][fn][2], acc[fm][fn][3]);
            if constexpr (MODE == 1) {
                float2 bb = *reinterpret_cast<const float2*>(bias + col);
                v0.x += bb.x; v0.y += bb.y; v1.x += bb.x; v1.y += bb.y;
            } else {
                if (col >= ZC) continue;
                v0.x = f2tf32(v0.x); v0.y = f2tf32(v0.y);
                v1.x = f2tf32(v1.x); v1.y = f2tf32(v1.y);
            }
            *reinterpret_cast<float2*>(&C[(size_t)r0 * ldc + col]) = v0;
            *reinterpret_cast<float2*>(&C[(size_t)(r0 + 8) * ldc + col]) = v1;
        }
    }
}

// ---------------- launch ----------------
extern "C" void kernel_launch(void* const* d_in, const int* in_sizes, int n_in,
                              void* d_out, int out_size) {
    const float* x      = (const float*)d_in[0];
    const float* qkv_w  = (const float*)d_in[1];
    const float* qkv_b  = (const float*)d_in[2];
    const float* la_q   = (const float*)d_in[3];
    const float* lb_q   = (const float*)d_in[4];
    const float* la_v   = (const float*)d_in[5];
    const float* lb_v   = (const float*)d_in[6];
    const float* A_q    = (const float*)d_in[7];
    const float* B_q    = (const float*)d_in[8];
    const float* A_v    = (const float*)d_in[9];
    const float* B_v    = (const float*)d_in[10];
    const float* gate   = (const float*)d_in[11];
    const float* alpha  = (const float*)d_in[12];

    norms_kernel<<<32, 256>>>(A_q, B_q, A_v, B_v);
    scales_kernel<<<1, 32>>>(gate, alpha);
    build_kernel<<<216, 256>>>(A_q, la_q, A_v, la_v, B_q, lb_q, B_v, lb_v);
    convert_kernel<<<1536, 256>>>((const float4*)x, M_ROWS * DD / 4, 0);
    convert_kernel<<<432, 256>>>((const float4*)qkv_w, NOUT * DD / 4, 1);

    gemm_tf32<0><<<dim3(3, 64), 256>>>(nullptr, nullptr);                 // z
    gemm_tf32<1><<<dim3(18, 64), 256>>>(qkv_b, (float*)d_out);            // qkv + deltas
}

// round 6
// speedup vs baseline: 1.9678x; 1.9678x over previous
#include <cuda_runtime.h>
#include <cuda_fp16.h>
#include <cstdint>
#include <math.h>

// ---------------- problem constants ----------------
#define DD 768
#define RR 16
#define TT 8
#define M_ROWS 8192
#define NOUT 2304
#define KM2 160          // padded per-branch low-rank K (144 real + 16 zero)
#define ZW 384           // padded z width / Acat rows (320 real + 64 zero)
#define ACATR 384

// ---------------- static scratch ----------------
__device__ __align__(16) __half g_xt[M_ROWS * DD];
__device__ __align__(16) __half g_wt[NOUT * DD];
__device__ __align__(16) __half g_Acat[ACATR * DD];
__device__ __align__(16) __half g_Bqs[DD * KM2];
__device__ __align__(16) __half g_Bvs[DD * KM2];
__device__ __align__(16) __half g_z[M_ROWS * ZW];
__device__ float g_normsq[32];
__device__ float g_scaleq[TT];
__device__ float g_scalev[TT];
__device__ float g_acur;

// ---------------- helpers ----------------
__device__ __forceinline__ void cp16(void* sdst, const void* gsrc) {
    unsigned s = (unsigned)__cvta_generic_to_shared(sdst);
    asm volatile("cp.async.cg.shared.global [%0], [%1], 16;\n" :: "r"(s), "l"(gsrc));
}

__device__ __forceinline__ void ldm_x4(uint32_t& d0, uint32_t& d1, uint32_t& d2,
                                       uint32_t& d3, uint32_t saddr) {
    asm volatile("ldmatrix.sync.aligned.m8n8.x4.shared.b16 {%0,%1,%2,%3}, [%4];"
                 : "=r"(d0), "=r"(d1), "=r"(d2), "=r"(d3) : "r"(saddr));
}

__device__ __forceinline__ void mma_fp16(float c[4], const uint32_t a[4], const uint32_t b[2]) {
    asm volatile(
        "mma.sync.aligned.m16n8k16.row.col.f32.f16.f16.f32 "
        "{%0,%1,%2,%3},{%4,%5,%6,%7},{%8,%9},{%0,%1,%2,%3};\n"
        : "+f"(c[0]), "+f"(c[1]), "+f"(c[2]), "+f"(c[3])
        : "r"(a[0]), "r"(a[1]), "r"(a[2]), "r"(a[3]),
          "r"(b[0]), "r"(b[1]));
}

// ---------------- prepass kernels ----------------
__global__ void norms_kernel(const float* __restrict__ Aq, const float* __restrict__ Bq,
                             const float* __restrict__ Av, const float* __restrict__ Bv) {
    __shared__ float red[256];
    int b = blockIdx.x, which = b >> 3, t = b & 7;
    const float* p = (which == 0) ? Aq : (which == 1) ? Bq : (which == 2) ? Av : Bv;
    p += t * (RR * DD);
    float s = 0.f;
    for (int i = threadIdx.x; i < RR * DD; i += 256) { float v = p[i]; s += v * v; }
    red[threadIdx.x] = s;
    __syncthreads();
    for (int o = 128; o > 0; o >>= 1) {
        if (threadIdx.x < o) red[threadIdx.x] += red[threadIdx.x + o];
        __syncthreads();
    }
    if (threadIdx.x == 0) g_normsq[b] = red[0];
}

__global__ void scales_kernel(const float* __restrict__ gate, const float* __restrict__ alpha) {
    if (threadIdx.x == 0) {
        float mx = gate[0];
        for (int t = 1; t < TT; t++) mx = fmaxf(mx, gate[t]);
        float e[TT], se = 0.f;
        for (int t = 0; t < TT; t++) { e[t] = expf(gate[t] - mx); se += e[t]; }
        for (int t = 0; t < TT; t++) {
            float beta = e[t] / se;
            g_scaleq[t] = beta / (sqrtf(g_normsq[t]) * sqrtf(g_normsq[8 + t]));
            g_scalev[t] = beta / (sqrtf(g_normsq[16 + t]) * sqrtf(g_normsq[24 + t]));
        }
        g_acur = alpha[TT];
    }
}

// Acat [384][768]: q rows 0-143 (+16 pad), v rows 160-303 (+16 pad), 320-383 zero.
// Bqs/Bvs [768][160]: cols 0-127 MoE (scaled), 128-143 LoRA (*alpha), 144-159 zero.
__global__ void build_kernel(const float* __restrict__ Aq, const float* __restrict__ laq,
                             const float* __restrict__ Av, const float* __restrict__ lav,
                             const float* __restrict__ Bq, const float* __restrict__ lbq,
                             const float* __restrict__ Bv, const float* __restrict__ lbv) {
    int i0 = blockIdx.x * blockDim.x + threadIdx.x;
    int stride = gridDim.x * blockDim.x;
    for (int i = i0; i < ACATR * DD; i += stride) {
        int j = i / DD, d = i % DD;
        float v = 0.f;
        if (j < 128)       v = Aq[j * DD + d];
        else if (j < 144)  v = laq[(j - 128) * DD + d];
        else if (j < 160)  v = 0.f;
        else if (j < 288)  v = Av[(j - 160) * DD + d];
        else if (j < 304)  v = lav[(j - 288) * DD + d];
        g_Acat[i] = __float2half_rn(v);
    }
    for (int i = i0; i < DD * KM2; i += stride) {
        int d = i / KM2, j = i % KM2;
        float vq = 0.f, vv = 0.f;
        if (j < 128) {
            int t = j >> 4, r = j & 15;
            vq = Bq[t * (DD * RR) + d * RR + r] * g_scaleq[t];
            vv = Bv[t * (DD * RR) + d * RR + r] * g_scalev[t];
        } else if (j < 144) {
            vq = lbq[d * RR + (j - 128)] * g_acur;
            vv = lbv[d * RR + (j - 128)] * g_acur;
        }
        g_Bqs[i] = __float2half_rn(vq);
        g_Bvs[i] = __float2half_rn(vv);
    }
}

// fp32 -> fp16 copy: which=0 -> g_xt, which=1 -> g_wt
__global__ void convert_kernel(const float4* __restrict__ src, int n4, int which) {
    __half2* dst = (which == 0) ? (__half2*)g_xt : (__half2*)g_wt;
    int i = blockIdx.x * blockDim.x + threadIdx.x;
    int st = gridDim.x * blockDim.x;
    for (; i < n4; i += st) {
        float4 v = src[i];
        dst[2 * i]     = __floats2half2_rn(v.x, v.y);
        dst[2 * i + 1] = __floats2half2_rn(v.z, v.w);
    }
}

// ---------------- fp16 mma.sync GEMM ----------------
// MODE 0: z[8192,384](fp16) = xt @ Acat^T       (K=768)
// MODE 1: out[8192,2304](f32) = xt @ wt^T + bias, fused low-rank K2=160:
//         n in [0,768):     += z[:, 0:160]  @ Bqs^T
//         n in [1536,2304): += z[:,160:320] @ Bvs^T
#define NS 3
#define BM 128
#define BN 128
#define BK 32
#define LDSH 40   // padded row length in halves (80 B) -> conflict-free ldmatrix

template <int MODE>
__global__ __launch_bounds__(256, 2) void gemm_fp16(const float* __restrict__ bias,
                                                    float* __restrict__ Cout) {
    extern __shared__ __half sm[];
    __half* As = sm;                       // [NS][BM][LDSH]
    __half* Bs = sm + NS * BM * LDSH;      // [NS][BN][LDSH]

    const int tid = threadIdx.x, lane = tid & 31, w = tid >> 5;
    const int g = lane >> 2, tg = lane & 3;
    const int wm = (w >> 2) * 64, wn = (w & 3) * 32;   // 2x4 warp grid, 64x32 tiles
    const int rowbase = blockIdx.y * BM, colbase = blockIdx.x * BN;

    const __half* Ap1 = g_xt + (size_t)rowbase * DD;
    const __half* Bp1;
    const __half* Ap2 = nullptr;
    const __half* Bp2 = nullptr;
    int KT2 = 0;
    if constexpr (MODE == 0) {
        Bp1 = g_Acat + (size_t)colbase * DD;
    } else {
        Bp1 = g_wt + (size_t)colbase * DD;
        if (colbase < DD) {
            KT2 = KM2 / BK;  // 5
            Ap2 = g_z + (size_t)rowbase * ZW;
            Bp2 = g_Bqs + (size_t)colbase * KM2;
        } else if (colbase >= 2 * DD) {
            KT2 = KM2 / BK;
            Ap2 = g_z + (size_t)rowbase * ZW + KM2;
            Bp2 = g_Bvs + (size_t)(colbase - 2 * DD) * KM2;
        }
    }
    constexpr int KT1 = DD / BK;  // 24
    const int KT = KT1 + KT2;

    float acc[4][4][4];
#pragma unroll
    for (int i = 0; i < 4; i++)
#pragma unroll
        for (int j = 0; j < 4; j++)
#pragma unroll
            for (int k = 0; k < 4; k++) acc[i][j][k] = 0.f;

    auto load_tile = [&](int stg, int kt) {
        const __half* Ap; const __half* Bp;
        int la, lb, kc;
        if (kt < KT1) { Ap = Ap1; la = DD; Bp = Bp1; lb = DD;  kc = kt * BK; }
        else          { Ap = Ap2; la = ZW; Bp = Bp2; lb = KM2; kc = (kt - KT1) * BK; }
        __half* Ad = As + stg * (BM * LDSH);
        __half* Bd = Bs + stg * (BN * LDSH);
#pragma unroll
        for (int i = 0; i < 2; i++) {
            int v = tid + i * 256, r = v >> 2, c = (v & 3) << 3;  // 16B = 8 halves
            cp16(Ad + r * LDSH + c, Ap + (size_t)r * la + kc + c);
            cp16(Bd + r * LDSH + c, Bp + (size_t)r * lb + kc + c);
        }
    };

    load_tile(0, 0);
    asm volatile("cp.async.commit_group;\n" ::);
    load_tile(1, 1);
    asm volatile("cp.async.commit_group;\n" ::);

    const uint32_t a_base = (uint32_t)__cvta_generic_to_shared(As);
    const uint32_t b_base = (uint32_t)__cvta_generic_to_shared(Bs);
    // per-thread invariant ldmatrix addressing
    const int a_row = wm + (lane & 15);
    const int a_csel = (lane >> 4) << 3;                        // 0 or 8
    const int b_row = wn + (lane & 7) + ((lane >> 4) << 3);     // n index
    const int b_csel = ((lane >> 3) & 1) << 3;                  // 0 or 8

    for (int kt = 0; kt < KT; kt++) {
        const int stg = kt % NS;
        if (kt == KT - 1) asm volatile("cp.async.wait_group 0;\n" ::);
        else              asm volatile("cp.async.wait_group 1;\n" ::);
        __syncthreads();
        if (kt + 2 < KT) {
            load_tile((kt + 2) % NS, kt + 2);
            asm volatile("cp.async.commit_group;\n" ::);
        }
#pragma unroll
        for (int ks = 0; ks < 2; ks++) {
            const int kk = ks * 16;
            uint32_t afr[4][4], bfr[4][2];
#pragma unroll
            for (int fm = 0; fm < 4; fm++) {
                uint32_t addr = a_base +
                    (uint32_t)(((stg * BM) + a_row + fm * 16) * LDSH + kk + a_csel) * 2;
                ldm_x4(afr[fm][0], afr[fm][1], afr[fm][2], afr[fm][3], addr);
            }
#pragma unroll
            for (int fn2 = 0; fn2 < 2; fn2++) {
                uint32_t addr = b_base +
                    (uint32_t)(((stg * BN) + b_row + fn2 * 16) * LDSH + kk + b_csel) * 2;
                uint32_t r0, r1, r2, r3;
                ldm_x4(r0, r1, r2, r3, addr);
                bfr[fn2 * 2][0] = r0;     bfr[fn2 * 2][1] = r1;
                bfr[fn2 * 2 + 1][0] = r2; bfr[fn2 * 2 + 1][1] = r3;
            }
#pragma unroll
            for (int fm = 0; fm < 4; fm++)
#pragma unroll
                for (int fn = 0; fn < 4; fn++)
                    mma_fp16(acc[fm][fn], afr[fm], bfr[fn]);
        }
    }

    // epilogue
#pragma unroll
    for (int fm = 0; fm < 4; fm++) {
        int r0 = rowbase + wm + fm * 16 + g;
#pragma unroll
        for (int fn = 0; fn < 4; fn++) {
            int col = colbase + wn + fn * 8 + 2 * tg;
            if constexpr (MODE == 1) {
                float2 bb = *reinterpret_cast<const float2*>(bias + col);
                float2 v0 = make_float2(acc[fm][fn][0] + bb.x, acc[fm][fn][1] + bb.y);
                float2 v1 = make_float2(acc[fm][fn][2] + bb.x, acc[fm][fn][3] + bb.y);
                *reinterpret_cast<float2*>(&Cout[(size_t)r0 * NOUT + col]) = v0;
                *reinterpret_cast<float2*>(&Cout[(size_t)(r0 + 8) * NOUT + col]) = v1;
            } else {
                __half2 h0 = __floats2half2_rn(acc[fm][fn][0], acc[fm][fn][1]);
                __half2 h1 = __floats2half2_rn(acc[fm][fn][2], acc[fm][fn][3]);
                *reinterpret_cast<__half2*>(&g_z[(size_t)r0 * ZW + col]) = h0;
                *reinterpret_cast<__half2*>(&g_z[(size_t)(r0 + 8) * ZW + col]) = h1;
            }
        }
    }
}

// ---------------- launch ----------------
extern "C" void kernel_launch(void* const* d_in, const int* in_sizes, int n_in,
                              void* d_out, int out_size) {
    const float* x     = (const float*)d_in[0];
    const float* qkv_w = (const float*)d_in[1];
    const float* qkv_b = (const float*)d_in[2];
    const float* la_q  = (const float*)d_in[3];
    const float* lb_q  = (const float*)d_in[4];
    const float* la_v  = (const float*)d_in[5];
    const float* lb_v  = (const float*)d_in[6];
    const float* A_q   = (const float*)d_in[7];
    const float* B_q   = (const float*)d_in[8];
    const float* A_v   = (const float*)d_in[9];
    const float* B_v   = (const float*)d_in[10];
    const float* gate  = (const float*)d_in[11];
    const float* alpha = (const float*)d_in[12];

    const int SMEM = NS * (BM + BN) * LDSH * (int)sizeof(__half);  // 61440
    cudaFuncSetAttribute((const void*)gemm_fp16<0>,
                         cudaFuncAttributeMaxDynamicSharedMemorySize, SMEM);
    cudaFuncSetAttribute((const void*)gemm_fp16<1>,
                         cudaFuncAttributeMaxDynamicSharedMemorySize, SMEM);

    norms_kernel<<<32, 256>>>(A_q, B_q, A_v, B_v);
    scales_kernel<<<1, 32>>>(gate, alpha);
    build_kernel<<<216, 256>>>(A_q, la_q, A_v, la_v, B_q, lb_q, B_v, lb_v);
    convert_kernel<<<1536, 256>>>((const float4*)x, M_ROWS * DD / 4, 0);
    convert_kernel<<<432, 256>>>((const float4*)qkv_w, NOUT * DD / 4, 1);

    // z = xt @ Acat^T : 3 col tiles x 64 row tiles
    gemm_fp16<0><<<dim3(3, 64), 256, SMEM>>>(nullptr, nullptr);
    // out = xt @ wt^T + bias (+ fused low-rank): 18 x 64 tiles
    gemm_fp16<1><<<dim3(18, 64), 256, SMEM>>>(qkv_b, (float*)d_out);
}

// round 8
// speedup vs baseline: 2.5096x; 1.2753x over previous
#include <cuda_runtime.h>
#include <cuda_fp16.h>
#include <cstdint>
#include <math.h>

// ---------------- problem constants ----------------
#define DD 768
#define RR 16
#define TT 8
#define M_ROWS 8192
#define NOUT 2304
#define KM2 160          // padded low-rank K per branch (144 real + 16 zero)

// ---------------- static scratch ----------------
__device__ __align__(16) __half g_xt[M_ROWS * DD];    // x in fp16
__device__ __align__(16) __half g_wt[NOUT * DD];      // W (+ folded dW) in fp16
__device__ __align__(16) __half g_Bqs[DD * KM2];      // scaled B_q  [e][j]
__device__ __align__(16) __half g_Bvs[DD * KM2];
__device__ __align__(16) __half g_AqT[DD * KM2];      // A_q^T       [d][j]
__device__ __align__(16) __half g_AvT[DD * KM2];
__device__ float g_normsq[32];                        // [Aq(8),Bq(8),Av(8),Bv(8)]

// ---------------- helpers ----------------
__device__ __forceinline__ void cp16(void* sdst, const void* gsrc) {
    unsigned s = (unsigned)__cvta_generic_to_shared(sdst);
    asm volatile("cp.async.cg.shared.global [%0], [%1], 16;\n" :: "r"(s), "l"(gsrc));
}

__device__ __forceinline__ void ldm_x4(uint32_t& d0, uint32_t& d1, uint32_t& d2,
                                       uint32_t& d3, uint32_t saddr) {
    asm volatile("ldmatrix.sync.aligned.m8n8.x4.shared.b16 {%0,%1,%2,%3}, [%4];"
                 : "=r"(d0), "=r"(d1), "=r"(d2), "=r"(d3) : "r"(saddr));
}

__device__ __forceinline__ void mma_fp16(float c[4], const uint32_t a[4], const uint32_t b[2]) {
    asm volatile(
        "mma.sync.aligned.m16n8k16.row.col.f32.f16.f16.f32 "
        "{%0,%1,%2,%3},{%4,%5,%6,%7},{%8,%9},{%0,%1,%2,%3};\n"
        : "+f"(c[0]), "+f"(c[1]), "+f"(c[2]), "+f"(c[3])
        : "r"(a[0]), "r"(a[1]), "r"(a[2]), "r"(a[3]),
          "r"(b[0]), "r"(b[1]));
}

// ---------------- prepass ----------------
__global__ void norms_kernel(const float* __restrict__ Aq, const float* __restrict__ Bq,
                             const float* __restrict__ Av, const float* __restrict__ Bv) {
    __shared__ float red[256];
    int b = blockIdx.x, which = b >> 3, t = b & 7;
    const float* p = (which == 0) ? Aq : (which == 1) ? Bq : (which == 2) ? Av : Bv;
    p += t * (RR * DD);
    float s = 0.f;
    for (int i = threadIdx.x; i < RR * DD; i += 256) { float v = p[i]; s += v * v; }
    red[threadIdx.x] = s;
    __syncthreads();
    for (int o = 128; o > 0; o >>= 1) {
        if (threadIdx.x < o) red[threadIdx.x] += red[threadIdx.x + o];
        __syncthreads();
    }
    if (threadIdx.x == 0) g_normsq[b] = red[0];
}

// Builds (fp16): Bqs/Bvs [768][160] with beta/norm (or alpha) folded in,
// and AqT/AvT [768][160] = transposed A stacks. Softmax recomputed per thread.
__global__ void build_kernel(const float* __restrict__ Aq, const float* __restrict__ laq,
                             const float* __restrict__ Av, const float* __restrict__ lav,
                             const float* __restrict__ Bq, const float* __restrict__ lbq,
                             const float* __restrict__ Bv, const float* __restrict__ lbv,
                             const float* __restrict__ gate, const float* __restrict__ alpha) {
    float sq[TT], sv[TT];
    {
        float mx = gate[0];
        for (int t = 1; t < TT; t++) mx = fmaxf(mx, gate[t]);
        float e[TT], se = 0.f;
        for (int t = 0; t < TT; t++) { e[t] = expf(gate[t] - mx); se += e[t]; }
        for (int t = 0; t < TT; t++) {
            float beta = e[t] / se;
            sq[t] = beta / (sqrtf(g_normsq[t]) * sqrtf(g_normsq[8 + t]));
            sv[t] = beta / (sqrtf(g_normsq[16 + t]) * sqrtf(g_normsq[24 + t]));
        }
    }
    float acur = alpha[TT];
    int i0 = blockIdx.x * blockDim.x + threadIdx.x;
    int stride = gridDim.x * blockDim.x;
    for (int i = i0; i < DD * KM2; i += stride) {
        int d = i / KM2, j = i % KM2;
        float bq = 0.f, bv = 0.f, aq = 0.f, av = 0.f;
        if (j < 128) {
            int t = j >> 4, r = j & 15;
            bq = Bq[t * (DD * RR) + d * RR + r] * sq[t];
            bv = Bv[t * (DD * RR) + d * RR + r] * sv[t];
            aq = Aq[j * DD + d];
            av = Av[j * DD + d];
        } else if (j < 144) {
            bq = lbq[d * RR + (j - 128)] * acur;
            bv = lbv[d * RR + (j - 128)] * acur;
            aq = laq[(j - 128) * DD + d];
            av = lav[(j - 128) * DD + d];
        }
        g_Bqs[i] = __float2half_rn(bq);
        g_Bvs[i] = __float2half_rn(bv);
        g_AqT[i] = __float2half_rn(aq);
        g_AvT[i] = __float2half_rn(av);
    }
}

// fp32 -> fp16, exactly-covering 4-way ILP (no bounds, no loop carry).
// which=0: x (grid 1536), which=1: qkv_w (grid 432)
__global__ void convert_kernel(const float4* __restrict__ src, int which) {
    __half2* dst = (which == 0) ? (__half2*)g_xt : (__half2*)g_wt;
    const int st = gridDim.x * blockDim.x;
    int i = blockIdx.x * blockDim.x + threadIdx.x;
    float4 v0 = src[i], v1 = src[i + st], v2 = src[i + 2 * st], v3 = src[i + 3 * st];
    dst[2 * i] = __floats2half2_rn(v0.x, v0.y);
    dst[2 * i + 1] = __floats2half2_rn(v0.z, v0.w);
    dst[2 * (i + st)] = __floats2half2_rn(v1.x, v1.y);
    dst[2 * (i + st) + 1] = __floats2half2_rn(v1.z, v1.w);
    dst[2 * (i + 2 * st)] = __floats2half2_rn(v2.x, v2.y);
    dst[2 * (i + 2 * st) + 1] = __floats2half2_rn(v2.z, v2.w);
    dst[2 * (i + 3 * st)] = __floats2half2_rn(v3.x, v3.y);
    dst[2 * (i + 3 * st) + 1] = __floats2half2_rn(v3.z, v3.w);
}

// ---------------- fp16 mma.sync GEMM machinery ----------------
#define NS 3
#define BM 128
#define BN 128
#define BK 32
#define LDSH 40   // padded row (80 B): conflict-free ldmatrix

// MODE 0 (delta): W'[e,d] = fp16( qkv_w[e_glob,d] + sum_j Bs[e,j]*AT[d,j] )
//   grid (6,6,2): z=0 -> q branch (e_glob=e), z=1 -> v branch (e_glob=1536+e), KT=5
// MODE 1 (main): out[8192,2304] = xt @ wt^T + bias, KT=24
template <int MODE>
__global__ __launch_bounds__(256, 2) void gemm_fp16(const float* __restrict__ wsrc,
                                                    float* __restrict__ Cout) {
    extern __shared__ __half sm[];
    __half* As = sm;
    __half* Bs = sm + NS * BM * LDSH;

    const int tid = threadIdx.x, lane = tid & 31, w = tid >> 5;
    const int g = lane >> 2, tg = lane & 3;
    const int wm = (w >> 2) * 64, wn = (w & 3) * 32;
    const int rowbase = blockIdx.y * BM, colbase = blockIdx.x * BN;

    const __half* Ap;
    const __half* Bp;
    int ld, KT;
    if constexpr (MODE == 0) {
        const __half* Asrc = blockIdx.z ? g_Bvs : g_Bqs;
        const __half* Bsrc = blockIdx.z ? g_AvT : g_AqT;
        Ap = Asrc + (size_t)rowbase * KM2;
        Bp = Bsrc + (size_t)colbase * KM2;
        ld = KM2; KT = KM2 / BK;          // 5
    } else {
        Ap = g_xt + (size_t)rowbase * DD;
        Bp = g_wt + (size_t)colbase * DD;
        ld = DD; KT = DD / BK;            // 24
    }

    float acc[4][4][4];
#pragma unroll
    for (int i = 0; i < 4; i++)
#pragma unroll
        for (int j = 0; j < 4; j++)
#pragma unroll
            for (int k = 0; k < 4; k++) acc[i][j][k] = 0.f;

    auto load_tile = [&](int stg, int kt) {
        int kc = kt * BK;
        __half* Ad = As + stg * (BM * LDSH);
        __half* Bd = Bs + stg * (BN * LDSH);
#pragma unroll
        for (int i = 0; i < 2; i++) {
            int v = tid + i * 256, r = v >> 2, c = (v & 3) << 3;
            cp16(Ad + r * LDSH + c, Ap + (size_t)r * ld + kc + c);
            cp16(Bd + r * LDSH + c, Bp + (size_t)r * ld + kc + c);
        }
    };

    load_tile(0, 0);
    asm volatile("cp.async.commit_group;\n" ::);
    load_tile(1, 1);
    asm volatile("cp.async.commit_group;\n" ::);

    const uint32_t a_base = (uint32_t)__cvta_generic_to_shared(As);
    const uint32_t b_base = (uint32_t)__cvta_generic_to_shared(Bs);
    const int a_row = wm + (lane & 15);
    const int a_csel = (lane >> 4) << 3;
    const int b_row = wn + (lane & 7) + ((lane >> 4) << 3);
    const int b_csel = ((lane >> 3) & 1) << 3;

    for (int kt = 0; kt < KT; kt++) {
        const int stg = kt % NS;
        if (kt == KT - 1) asm volatile("cp.async.wait_group 0;\n" ::);
        else              asm volatile("cp.async.wait_group 1;\n" ::);
        __syncthreads();
        if (kt + 2 < KT) {
            load_tile((kt + 2) % NS, kt + 2);
            asm volatile("cp.async.commit_group;\n" ::);
        }
#pragma unroll
        for (int ks = 0; ks < 2; ks++) {
            const int kk = ks * 16;
            uint32_t afr[4][4], bfr[4][2];
#pragma unroll
            for (int fm = 0; fm < 4; fm++) {
                uint32_t addr = a_base +
                    (uint32_t)(((stg * BM) + a_row + fm * 16) * LDSH + kk + a_csel) * 2;
                ldm_x4(afr[fm][0], afr[fm][1], afr[fm][2], afr[fm][3], addr);
            }
#pragma unroll
            for (int fn2 = 0; fn2 < 2; fn2++) {
                uint32_t addr = b_base +
                    (uint32_t)(((stg * BN) + b_row + fn2 * 16) * LDSH + kk + b_csel) * 2;
                uint32_t r0, r1, r2, r3;
                ldm_x4(r0, r1, r2, r3, addr);
                bfr[fn2 * 2][0] = r0;     bfr[fn2 * 2][1] = r1;
                bfr[fn2 * 2 + 1][0] = r2; bfr[fn2 * 2 + 1][1] = r3;
            }
#pragma unroll
            for (int fm = 0; fm < 4; fm++)
#pragma unroll
                for (int fn = 0; fn < 4; fn++)
                    mma_fp16(acc[fm][fn], afr[fm], bfr[fn]);
        }
    }

    // epilogue
#pragma unroll
    for (int fm = 0; fm < 4; fm++) {
        int r0 = rowbase + wm + fm * 16 + g;
#pragma unroll
        for (int fn = 0; fn < 4; fn++) {
            int col = colbase + wn + fn * 8 + 2 * tg;
            if constexpr (MODE == 1) {
                // wsrc = bias
                float2 bb = *reinterpret_cast<const float2*>(wsrc + col);
                float2 v0 = make_float2(acc[fm][fn][0] + bb.x, acc[fm][fn][1] + bb.y);
                float2 v1 = make_float2(acc[fm][fn][2] + bb.x, acc[fm][fn][3] + bb.y);
                *reinterpret_cast<float2*>(&Cout[(size_t)r0 * NOUT + col]) = v0;
                *reinterpret_cast<float2*>(&Cout[(size_t)(r0 + 8) * NOUT + col]) = v1;
            } else {
                // wsrc = qkv_w (f32); add delta in f32, round once to fp16
                int e0 = (blockIdx.z ? 2 * DD : 0) + r0;
                float2 w0 = *reinterpret_cast<const float2*>(&wsrc[(size_t)e0 * DD + col]);
                float2 w1 = *reinterpret_cast<const float2*>(&wsrc[(size_t)(e0 + 8) * DD + col]);
                __half2 h0 = __floats2half2_rn(acc[fm][fn][0] + w0.x, acc[fm][fn][1] + w0.y);
                __half2 h1 = __floats2half2_rn(acc[fm][fn][2] + w1.x, acc[fm][fn][3] + w1.y);
                *reinterpret_cast<__half2*>(&g_wt[(size_t)e0 * DD + col]) = h0;
                *reinterpret_cast<__half2*>(&g_wt[(size_t)(e0 + 8) * DD + col]) = h1;
            }
        }
    }
}

// ---------------- launch ----------------
extern "C" void kernel_launch(void* const* d_in, const int* in_sizes, int n_in,
                              void* d_out, int out_size) {
    const float* x     = (const float*)d_in[0];
    const float* qkv_w = (const float*)d_in[1];
    const float* qkv_b = (const float*)d_in[2];
    const float* la_q  = (const float*)d_in[3];
    const float* lb_q  = (const float*)d_in[4];
    const float* la_v  = (const float*)d_in[5];
    const float* lb_v  = (const float*)d_in[6];
    const float* A_q   = (const float*)d_in[7];
    const float* B_q   = (const float*)d_in[8];
    const float* A_v   = (const float*)d_in[9];
    const float* B_v   = (const float*)d_in[10];
    const float* gate  = (const float*)d_in[11];
    const float* alpha = (const float*)d_in[12];

    const int SMEM = NS * (BM + BN) * LDSH * (int)sizeof(__half);  // 61440
    cudaFuncSetAttribute((const void*)gemm_fp16<0>,
                         cudaFuncAttributeMaxDynamicSharedMemorySize, SMEM);
    cudaFuncSetAttribute((const void*)gemm_fp16<1>,
                         cudaFuncAttributeMaxDynamicSharedMemorySize, SMEM);

    norms_kernel<<<32, 256>>>(A_q, B_q, A_v, B_v);
    build_kernel<<<120, 256>>>(A_q, la_q, A_v, la_v, B_q, lb_q, B_v, lb_v, gate, alpha);
    convert_kernel<<<1536, 256>>>((const float4*)x, 0);       // 1536*256*4 = 8192*768/4
    convert_kernel<<<432, 256>>>((const float4*)qkv_w, 1);    // 432*256*4 = 2304*768/4

    // Fold low-rank into weights: W'[q rows, v rows] = W + B_s @ A^T
    gemm_fp16<0><<<dim3(6, 6, 2), 256, SMEM>>>(qkv_w, nullptr);

    // Main GEMM: out = xt @ wt^T + bias  (uniform K=768)
    gemm_fp16<1><<<dim3(18, 64, 1), 256, SMEM>>>(qkv_b, (float*)d_out);
}

// round 9
// speedup vs baseline: 2.5888x; 1.0316x over previous
#include <cuda_runtime.h>
#include <cuda_fp16.h>
#include <cstdint>
#include <math.h>

// ---------------- problem constants ----------------
#define DD 768
#define RR 16
#define TT 8
#define M_ROWS 8192
#define NOUT 2304
#define KM2 192          // padded low-rank K per branch (144 real + 48 zero)

// ---------------- static scratch ----------------
__device__ __align__(16) __half g_xt[M_ROWS * DD];    // x in fp16
__device__ __align__(16) __half g_wt[NOUT * DD];      // W (+ folded dW) in fp16
__device__ __align__(16) __half g_Bqs[DD * KM2];      // scaled B_q  [e][j]
__device__ __align__(16) __half g_Bvs[DD * KM2];
__device__ __align__(16) __half g_AqT[DD * KM2];      // A_q^T       [d][j]
__device__ __align__(16) __half g_AvT[DD * KM2];
__device__ float g_normsq[32];                        // [Aq(8),Bq(8),Av(8),Bv(8)]

// ---------------- helpers ----------------
__device__ __forceinline__ void cp16(void* sdst, const void* gsrc) {
    unsigned s = (unsigned)__cvta_generic_to_shared(sdst);
    asm volatile("cp.async.cg.shared.global [%0], [%1], 16;\n" :: "r"(s), "l"(gsrc));
}

__device__ __forceinline__ void ldm_x4(uint32_t& d0, uint32_t& d1, uint32_t& d2,
                                       uint32_t& d3, uint32_t saddr) {
    asm volatile("ldmatrix.sync.aligned.m8n8.x4.shared.b16 {%0,%1,%2,%3}, [%4];"
                 : "=r"(d0), "=r"(d1), "=r"(d2), "=r"(d3) : "r"(saddr));
}

__device__ __forceinline__ void mma_fp16(float c[4], const uint32_t a[4], const uint32_t b[2]) {
    asm volatile(
        "mma.sync.aligned.m16n8k16.row.col.f32.f16.f16.f32 "
        "{%0,%1,%2,%3},{%4,%5,%6,%7},{%8,%9},{%0,%1,%2,%3};\n"
        : "+f"(c[0]), "+f"(c[1]), "+f"(c[2]), "+f"(c[3])
        : "r"(a[0]), "r"(a[1]), "r"(a[2]), "r"(a[3]),
          "r"(b[0]), "r"(b[1]));
}

// ---------------- prepass ----------------
__global__ void norms_kernel(const float* __restrict__ Aq, const float* __restrict__ Bq,
                             const float* __restrict__ Av, const float* __restrict__ Bv) {
    __shared__ float red[1024];
    int b = blockIdx.x, which = b >> 3, t = b & 7;
    const float* p = (which == 0) ? Aq : (which == 1) ? Bq : (which == 2) ? Av : Bv;
    p += t * (RR * DD);
    float s = 0.f;
    for (int i = threadIdx.x; i < RR * DD; i += 1024) { float v = p[i]; s += v * v; }
    red[threadIdx.x] = s;
    __syncthreads();
    for (int o = 512; o > 0; o >>= 1) {
        if (threadIdx.x < o) red[threadIdx.x] += red[threadIdx.x + o];
        __syncthreads();
    }
    if (threadIdx.x == 0) g_normsq[b] = red[0];
}

// Builds (fp16): Bqs/Bvs [768][192] with beta/norm (or alpha) folded in,
// and AqT/AvT [768][192] = transposed A stacks. Cols 144-191 zero.
__global__ void build_kernel(const float* __restrict__ Aq, const float* __restrict__ laq,
                             const float* __restrict__ Av, const float* __restrict__ lav,
                             const float* __restrict__ Bq, const float* __restrict__ lbq,
                             const float* __restrict__ Bv, const float* __restrict__ lbv,
                             const float* __restrict__ gate, const float* __restrict__ alpha) {
    float sq[TT], sv[TT];
    {
        float mx = gate[0];
        for (int t = 1; t < TT; t++) mx = fmaxf(mx, gate[t]);
        float e[TT], se = 0.f;
        for (int t = 0; t < TT; t++) { e[t] = expf(gate[t] - mx); se += e[t]; }
        for (int t = 0; t < TT; t++) {
            float beta = e[t] / se;
            sq[t] = beta / (sqrtf(g_normsq[t]) * sqrtf(g_normsq[8 + t]));
            sv[t] = beta / (sqrtf(g_normsq[16 + t]) * sqrtf(g_normsq[24 + t]));
        }
    }
    float acur = alpha[TT];
    int i0 = blockIdx.x * blockDim.x + threadIdx.x;
    int stride = gridDim.x * blockDim.x;
    for (int i = i0; i < DD * KM2; i += stride) {
        int d = i / KM2, j = i % KM2;
        float bq = 0.f, bv = 0.f, aq = 0.f, av = 0.f;
        if (j < 128) {
            int t = j >> 4, r = j & 15;
            bq = Bq[t * (DD * RR) + d * RR + r] * sq[t];
            bv = Bv[t * (DD * RR) + d * RR + r] * sv[t];
            aq = Aq[j * DD + d];
            av = Av[j * DD + d];
        } else if (j < 144) {
            bq = lbq[d * RR + (j - 128)] * acur;
            bv = lbv[d * RR + (j - 128)] * acur;
            aq = laq[(j - 128) * DD + d];
            av = lav[(j - 128) * DD + d];
        }
        g_Bqs[i] = __float2half_rn(bq);
        g_Bvs[i] = __float2half_rn(bv);
        g_AqT[i] = __float2half_rn(aq);
        g_AvT[i] = __float2half_rn(av);
    }
}

// fp32 -> fp16 with 16B stores: thread handles 4 uint4 outputs (8 float4 reads).
// Exactly covering: gridDim*256*4 uint4 == total halves/8.
__global__ void convert_kernel(const float4* __restrict__ src, uint4* __restrict__ dst) {
    const int st = gridDim.x * blockDim.x;
    int i = blockIdx.x * blockDim.x + threadIdx.x;
#pragma unroll
    for (int u = 0; u < 4; u++) {
        int k = i + u * st;
        float4 a = src[2 * k], b = src[2 * k + 1];
        __half2 h0 = __floats2half2_rn(a.x, a.y);
        __half2 h1 = __floats2half2_rn(a.z, a.w);
        __half2 h2 = __floats2half2_rn(b.x, b.y);
        __half2 h3 = __floats2half2_rn(b.z, b.w);
        uint4 o;
        o.x = *reinterpret_cast<uint32_t*>(&h0);
        o.y = *reinterpret_cast<uint32_t*>(&h1);
        o.z = *reinterpret_cast<uint32_t*>(&h2);
        o.w = *reinterpret_cast<uint32_t*>(&h3);
        dst[k] = o;
    }
}

// ---------------- fp16 mma.sync GEMM machinery ----------------
#define NS 3
#define BM 128
#define BN 128
#define BK 64
#define LDSH 72   // padded row (144 B): 16B-step row offsets -> conflict-free ldmatrix

// MODE 0 (delta): W'[e,d] = fp16( qkv_w[e_glob,d] + sum_j Bs[e,j]*AT[d,j] ), KT=3
//   grid (6,6,2): z=0 -> q branch (e_glob=e), z=1 -> v branch (e_glob=1536+e)
// MODE 1 (main): out[8192,2304] = xt @ wt^T + bias, KT=12
template <int MODE>
__global__ __launch_bounds__(256, 2) void gemm_fp16(const float* __restrict__ wsrc,
                                                    float* __restrict__ Cout) {
    extern __shared__ __half sm[];
    __half* As = sm;
    __half* Bs = sm + NS * BM * LDSH;

    const int tid = threadIdx.x, lane = tid & 31, w = tid >> 5;
    const int g = lane >> 2, tg = lane & 3;
    const int wm = (w >> 2) * 64, wn = (w & 3) * 32;
    const int rowbase = blockIdx.y * BM, colbase = blockIdx.x * BN;

    const __half* Ap;
    const __half* Bp;
    int ld, KT;
    if constexpr (MODE == 0) {
        const __half* Asrc = blockIdx.z ? g_Bvs : g_Bqs;
        const __half* Bsrc = blockIdx.z ? g_AvT : g_AqT;
        Ap = Asrc + (size_t)rowbase * KM2;
        Bp = Bsrc + (size_t)colbase * KM2;
        ld = KM2; KT = KM2 / BK;          // 3
    } else {
        Ap = g_xt + (size_t)rowbase * DD;
        Bp = g_wt + (size_t)colbase * DD;
        ld = DD; KT = DD / BK;            // 12
    }

    float acc[4][4][4];
#pragma unroll
    for (int i = 0; i < 4; i++)
#pragma unroll
        for (int j = 0; j < 4; j++)
#pragma unroll
            for (int k = 0; k < 4; k++) acc[i][j][k] = 0.f;

    auto load_tile = [&](int stg, int kt) {
        int kc = kt * BK;
        __half* Ad = As + stg * (BM * LDSH);
        __half* Bd = Bs + stg * (BN * LDSH);
#pragma unroll
        for (int i = 0; i < 4; i++) {
            int v = tid + i * 256, r = v >> 3, c = (v & 7) << 3;   // 8 x 16B chunks/row
            cp16(Ad + r * LDSH + c, Ap + (size_t)r * ld + kc + c);
            cp16(Bd + r * LDSH + c, Bp + (size_t)r * ld + kc + c);
        }
    };

    load_tile(0, 0);
    asm volatile("cp.async.commit_group;\n" ::);
    load_tile(1, 1);
    asm volatile("cp.async.commit_group;\n" ::);

    const uint32_t a_base = (uint32_t)__cvta_generic_to_shared(As);
    const uint32_t b_base = (uint32_t)__cvta_generic_to_shared(Bs);
    const int a_row = wm + (lane & 15);
    const int a_csel = (lane >> 4) << 3;
    const int b_row = wn + (lane & 7) + ((lane >> 4) << 3);
    const int b_csel = ((lane >> 3) & 1) << 3;

    for (int kt = 0; kt < KT; kt++) {
        const int stg = kt % NS;
        if (kt == KT - 1) asm volatile("cp.async.wait_group 0;\n" ::);
        else              asm volatile("cp.async.wait_group 1;\n" ::);
        __syncthreads();
        if (kt + 2 < KT) {
            load_tile((kt + 2) % NS, kt + 2);
            asm volatile("cp.async.commit_group;\n" ::);
        }
#pragma unroll
        for (int ks = 0; ks < 4; ks++) {
            const int kk = ks * 16;
            uint32_t afr[4][4], bfr[4][2];
#pragma unroll
            for (int fm = 0; fm < 4; fm++) {
                uint32_t addr = a_base +
                    (uint32_t)(((stg * BM) + a_row + fm * 16) * LDSH + kk + a_csel) * 2;
                ldm_x4(afr[fm][0], afr[fm][1], afr[fm][2], afr[fm][3], addr);
            }
#pragma unroll
            for (int fn2 = 0; fn2 < 2; fn2++) {
                uint32_t addr = b_base +
                    (uint32_t)(((stg * BN) + b_row + fn2 * 16) * LDSH + kk + b_csel) * 2;
                uint32_t r0, r1, r2, r3;
                ldm_x4(r0, r1, r2, r3, addr);
                bfr[fn2 * 2][0] = r0;     bfr[fn2 * 2][1] = r1;
                bfr[fn2 * 2 + 1][0] = r2; bfr[fn2 * 2 + 1][1] = r3;
            }
#pragma unroll
            for (int fm = 0; fm < 4; fm++)
#pragma unroll
                for (int fn = 0; fn < 4; fn++)
                    mma_fp16(acc[fm][fn], afr[fm], bfr[fn]);
        }
    }

    // epilogue
#pragma unroll
    for (int fm = 0; fm < 4; fm++) {
        int r0 = rowbase + wm + fm * 16 + g;
#pragma unroll
        for (int fn = 0; fn < 4; fn++) {
            int col = colbase + wn + fn * 8 + 2 * tg;
            if constexpr (MODE == 1) {
                // wsrc = bias
                float2 bb = *reinterpret_cast<const float2*>(wsrc + col);
                float2 v0 = make_float2(acc[fm][fn][0] + bb.x, acc[fm][fn][1] + bb.y);
                float2 v1 = make_float2(acc[fm][fn][2] + bb.x, acc[fm][fn][3] + bb.y);
                *reinterpret_cast<float2*>(&Cout[(size_t)r0 * NOUT + col]) = v0;
                *reinterpret_cast<float2*>(&Cout[(size_t)(r0 + 8) * NOUT + col]) = v1;
            } else {
                // wsrc = qkv_w (f32); add delta in f32, round once to fp16
                int e0 = (blockIdx.z ? 2 * DD : 0) + r0;
                float2 w0 = *reinterpret_cast<const float2*>(&wsrc[(size_t)e0 * DD + col]);
                float2 w1 = *reinterpret_cast<const float2*>(&wsrc[(size_t)(e0 + 8) * DD + col]);
                __half2 h0 = __floats2half2_rn(acc[fm][fn][0] + w0.x, acc[fm][fn][1] + w0.y);
                __half2 h1 = __floats2half2_rn(acc[fm][fn][2] + w1.x, acc[fm][fn][3] + w1.y);
                *reinterpret_cast<__half2*>(&g_wt[(size_t)e0 * DD + col]) = h0;
                *reinterpret_cast<__half2*>(&g_wt[(size_t)(e0 + 8) * DD + col]) = h1;
            }
        }
    }
}

// ---------------- launch ----------------
extern "C" void kernel_launch(void* const* d_in, const int* in_sizes, int n_in,
                              void* d_out, int out_size) {
    const float* x     = (const float*)d_in[0];
    const float* qkv_w = (const float*)d_in[1];
    const float* qkv_b = (const float*)d_in[2];
    const float* la_q  = (const float*)d_in[3];
    const float* lb_q  = (const float*)d_in[4];
    const float* la_v  = (const float*)d_in[5];
    const float* lb_v  = (const float*)d_in[6];
    const float* A_q   = (const float*)d_in[7];
    const float* B_q   = (const float*)d_in[8];
    const float* A_v   = (const float*)d_in[9];
    const float* B_v   = (const float*)d_in[10];
    const float* gate  = (const float*)d_in[11];
    const float* alpha = (const float*)d_in[12];

    const int SMEM = NS * (BM + BN) * LDSH * (int)sizeof(__half);  // 110592
    cudaFuncSetAttribute((const void*)gemm_fp16<0>,
                         cudaFuncAttributeMaxDynamicSharedMemorySize, SMEM);
    cudaFuncSetAttribute((const void*)gemm_fp16<1>,
                         cudaFuncAttributeMaxDynamicSharedMemorySize, SMEM);

    void *pXt, *pWt;
    cudaGetSymbolAddress(&pXt, g_xt);
    cudaGetSymbolAddress(&pWt, g_wt);

    norms_kernel<<<32, 1024>>>(A_q, B_q, A_v, B_v);
    build_kernel<<<144, 256>>>(A_q, la_q, A_v, la_v, B_q, lb_q, B_v, lb_v, gate, alpha);
    // x: 8192*768 halves = 786432 uint4 -> 768 blocks * 256 thr * 4
    convert_kernel<<<768, 256>>>((const float4*)x, (uint4*)pXt);
    // w middle third only (k rows 768..1535): 768*768 halves = 73728 uint4 -> 72 blocks
    convert_kernel<<<72, 256>>>((const float4*)(qkv_w + (size_t)DD * DD),
                                (uint4*)((__half*)pWt + (size_t)DD * DD));

    // Fold low-rank into weights: W'[q rows, v rows] = W + B_s @ A^T  (writes g_wt q/v thirds)
    gemm_fp16<0><<<dim3(6, 6, 2), 256, SMEM>>>(qkv_w, nullptr);

    // Main GEMM: out = xt @ wt^T + bias  (uniform K=768)
    gemm_fp16<1><<<dim3(18, 64, 1), 256, SMEM>>>(qkv_b, (float*)d_out);
}

// round 10
// speedup vs baseline: 2.7697x; 1.0699x over previous
#include <cuda_runtime.h>
#include <cuda_fp16.h>
#include <cstdint>
#include <math.h>

// ---------------- problem constants ----------------
#define DD 768
#define RR 16
#define TT 8
#define M_ROWS 8192
#define NOUT 2304
#define KM2 192          // padded low-rank K per branch (144 real + 48 zero)

// ---------------- static scratch ----------------
__device__ __align__(16) __half g_xt[M_ROWS * DD];    // x in fp16
__device__ __align__(16) __half g_wt[NOUT * DD];      // W (+ folded dW) in fp16
__device__ __align__(16) __half g_Bqs[DD * KM2];      // scaled B_q  [e][j]
__device__ __align__(16) __half g_Bvs[DD * KM2];
__device__ __align__(16) __half g_AqT[DD * KM2];      // A_q^T       [d][j]
__device__ __align__(16) __half g_AvT[DD * KM2];
__device__ float g_normsq[32];                        // [Aq(8),Bq(8),Av(8),Bv(8)]

// ---------------- helpers ----------------
__device__ __forceinline__ void cp16(void* sdst, const void* gsrc) {
    unsigned s = (unsigned)__cvta_generic_to_shared(sdst);
    asm volatile("cp.async.cg.shared.global [%0], [%1], 16;\n" :: "r"(s), "l"(gsrc));
}

__device__ __forceinline__ void ldm_x4(uint32_t& d0, uint32_t& d1, uint32_t& d2,
                                       uint32_t& d3, uint32_t saddr) {
    asm volatile("ldmatrix.sync.aligned.m8n8.x4.shared.b16 {%0,%1,%2,%3}, [%4];"
                 : "=r"(d0), "=r"(d1), "=r"(d2), "=r"(d3) : "r"(saddr));
}

__device__ __forceinline__ void mma_fp16(float c[4], const uint32_t a[4], const uint32_t b[2]) {
    asm volatile(
        "mma.sync.aligned.m16n8k16.row.col.f32.f16.f16.f32 "
        "{%0,%1,%2,%3},{%4,%5,%6,%7},{%8,%9},{%0,%1,%2,%3};\n"
        : "+f"(c[0]), "+f"(c[1]), "+f"(c[2]), "+f"(c[3])
        : "r"(a[0]), "r"(a[1]), "r"(a[2]), "r"(a[3]),
          "r"(b[0]), "r"(b[1]));
}

// ---------------- fused prepass: x-convert | w-convert | norms ----------------
// Segmented grid (256 threads/block):
//   blocks [0,768):    x fp32->fp16      (768*256*4 uint4 = 8192*768/8)
//   blocks [768,840):  w middle third    (72*256*4 uint4 = 768*768/8)
//   blocks [840,872):  Frobenius norm^2 of the 32 low-rank matrices
__device__ __forceinline__ void convert_seg(const float4* __restrict__ src,
                                            uint4* __restrict__ dst,
                                            int bid_local, int nb) {
    const int stride = nb * 256;
    int i = bid_local * 256 + threadIdx.x;
#pragma unroll
    for (int u = 0; u < 4; u++) {
        int k = i + u * stride;
        float4 a = src[2 * k], b = src[2 * k + 1];
        __half2 h0 = __floats2half2_rn(a.x, a.y);
        __half2 h1 = __floats2half2_rn(a.z, a.w);
        __half2 h2 = __floats2half2_rn(b.x, b.y);
        __half2 h3 = __floats2half2_rn(b.z, b.w);
        uint4 o;
        o.x = *reinterpret_cast<uint32_t*>(&h0);
        o.y = *reinterpret_cast<uint32_t*>(&h1);
        o.z = *reinterpret_cast<uint32_t*>(&h2);
        o.w = *reinterpret_cast<uint32_t*>(&h3);
        dst[k] = o;
    }
}

__global__ void prep_kernel(const float4* __restrict__ x, const float4* __restrict__ wmid,
                            const float* __restrict__ Aq, const float* __restrict__ Bq,
                            const float* __restrict__ Av, const float* __restrict__ Bv) {
    int bid = blockIdx.x;
    if (bid < 768) {
        convert_seg(x, (uint4*)g_xt, bid, 768);
    } else if (bid < 840) {
        convert_seg(wmid, (uint4*)(g_wt + (size_t)DD * DD), bid - 768, 72);
    } else {
        __shared__ float red[256];
        int b = bid - 840, which = b >> 3, t = b & 7;
        const float* p = (which == 0) ? Aq : (which == 1) ? Bq : (which == 2) ? Av : Bv;
        p += t * (RR * DD);
        float s = 0.f;
        for (int i = threadIdx.x; i < RR * DD; i += 256) { float v = p[i]; s += v * v; }
        red[threadIdx.x] = s;
        __syncthreads();
        for (int o = 128; o > 0; o >>= 1) {
            if (threadIdx.x < o) red[threadIdx.x] += red[threadIdx.x + o];
            __syncthreads();
        }
        if (threadIdx.x == 0) g_normsq[b] = red[0];
    }
}

// Builds (fp16): Bqs/Bvs [768][192] with beta/norm (or alpha) folded in,
// and AqT/AvT [768][192] = transposed A stacks. Cols 144-191 zero.
__global__ void build_kernel(const float* __restrict__ Aq, const float* __restrict__ laq,
                             const float* __restrict__ Av, const float* __restrict__ lav,
                             const float* __restrict__ Bq, const float* __restrict__ lbq,
                             const float* __restrict__ Bv, const float* __restrict__ lbv,
                             const float* __restrict__ gate, const float* __restrict__ alpha) {
    float sq[TT], sv[TT];
    {
        float mx = gate[0];
        for (int t = 1; t < TT; t++) mx = fmaxf(mx, gate[t]);
        float e[TT], se = 0.f;
        for (int t = 0; t < TT; t++) { e[t] = expf(gate[t] - mx); se += e[t]; }
        for (int t = 0; t < TT; t++) {
            float beta = e[t] / se;
            sq[t] = beta / (sqrtf(g_normsq[t]) * sqrtf(g_normsq[8 + t]));
            sv[t] = beta / (sqrtf(g_normsq[16 + t]) * sqrtf(g_normsq[24 + t]));
        }
    }
    float acur = alpha[TT];
    int i0 = blockIdx.x * blockDim.x + threadIdx.x;
    int stride = gridDim.x * blockDim.x;
    for (int i = i0; i < DD * KM2; i += stride) {
        int d = i / KM2, j = i % KM2;
        float bq = 0.f, bv = 0.f, aq = 0.f, av = 0.f;
        if (j < 128) {
            int t = j >> 4, r = j & 15;
            bq = Bq[t * (DD * RR) + d * RR + r] * sq[t];
            bv = Bv[t * (DD * RR) + d * RR + r] * sv[t];
            aq = Aq[j * DD + d];
            av = Av[j * DD + d];
        } else if (j < 144) {
            bq = lbq[d * RR + (j - 128)] * acur;
            bv = lbv[d * RR + (j - 128)] * acur;
            aq = laq[(j - 128) * DD + d];
            av = lav[(j - 128) * DD + d];
        }
        g_Bqs[i] = __float2half_rn(bq);
        g_Bvs[i] = __float2half_rn(bv);
        g_AqT[i] = __float2half_rn(aq);
        g_AvT[i] = __float2half_rn(av);
    }
}

// ---------------- fp16 mma.sync GEMM machinery ----------------
#define NS 3
#define BM 128
#define BN 128
#define BK 64
#define LDSH 72   // padded row (144 B): 16B-step row offsets -> conflict-free ldmatrix

// MODE 0 (delta): W'[e,d] = fp16( qkv_w[e_glob,d] + sum_j Bs[e,j]*AT[d,j] ), KT=3
//   grid (6,6,2): z=0 -> q branch (e_glob=e), z=1 -> v branch (e_glob=1536+e)
// MODE 1 (main): out[8192,2304] = xt @ wt^T + bias, KT=12
template <int MODE>
__global__ __launch_bounds__(256, 2) void gemm_fp16(const float* __restrict__ wsrc,
                                                    float* __restrict__ Cout) {
    extern __shared__ __half sm[];
    __half* As = sm;
    __half* Bs = sm + NS * BM * LDSH;

    const int tid = threadIdx.x, lane = tid & 31, w = tid >> 5;
    const int g = lane >> 2, tg = lane & 3;
    const int wm = (w >> 2) * 64, wn = (w & 3) * 32;
    const int rowbase = blockIdx.y * BM, colbase = blockIdx.x * BN;

    const __half* Ap;
    const __half* Bp;
    int ld, KT;
    if constexpr (MODE == 0) {
        const __half* Asrc = blockIdx.z ? g_Bvs : g_Bqs;
        const __half* Bsrc = blockIdx.z ? g_AvT : g_AqT;
        Ap = Asrc + (size_t)rowbase * KM2;
        Bp = Bsrc + (size_t)colbase * KM2;
        ld = KM2; KT = KM2 / BK;          // 3
    } else {
        Ap = g_xt + (size_t)rowbase * DD;
        Bp = g_wt + (size_t)colbase * DD;
        ld = DD; KT = DD / BK;            // 12
    }

    float acc[4][4][4];
#pragma unroll
    for (int i = 0; i < 4; i++)
#pragma unroll
        for (int j = 0; j < 4; j++)
#pragma unroll
            for (int k = 0; k < 4; k++) acc[i][j][k] = 0.f;

    auto load_tile = [&](int stg, int kt) {
        int kc = kt * BK;
        __half* Ad = As + stg * (BM * LDSH);
        __half* Bd = Bs + stg * (BN * LDSH);
#pragma unroll
        for (int i = 0; i < 4; i++) {
            int v = tid + i * 256, r = v >> 3, c = (v & 7) << 3;   // 8 x 16B chunks/row
            cp16(Ad + r * LDSH + c, Ap + (size_t)r * ld + kc + c);
            cp16(Bd + r * LDSH + c, Bp + (size_t)r * ld + kc + c);
        }
    };

    load_tile(0, 0);
    asm volatile("cp.async.commit_group;\n" ::);
    load_tile(1, 1);
    asm volatile("cp.async.commit_group;\n" ::);

    const uint32_t a_base = (uint32_t)__cvta_generic_to_shared(As);
    const uint32_t b_base = (uint32_t)__cvta_generic_to_shared(Bs);
    const int a_row = wm + (lane & 15);
    const int a_csel = (lane >> 4) << 3;
    const int b_row = wn + (lane & 7) + ((lane >> 4) << 3);
    const int b_csel = ((lane >> 3) & 1) << 3;

    for (int kt = 0; kt < KT; kt++) {
        const int stg = kt % NS;
        if (kt == KT - 1) asm volatile("cp.async.wait_group 0;\n" ::);
        else              asm volatile("cp.async.wait_group 1;\n" ::);
        __syncthreads();
        if (kt + 2 < KT) {
            load_tile((kt + 2) % NS, kt + 2);
            asm volatile("cp.async.commit_group;\n" ::);
        }
#pragma unroll
        for (int ks = 0; ks < 4; ks++) {
            const int kk = ks * 16;
            uint32_t afr[4][4], bfr[4][2];
#pragma unroll
            for (int fm = 0; fm < 4; fm++) {
                uint32_t addr = a_base +
                    (uint32_t)(((stg * BM) + a_row + fm * 16) * LDSH + kk + a_csel) * 2;
                ldm_x4(afr[fm][0], afr[fm][1], afr[fm][2], afr[fm][3], addr);
            }
#pragma unroll
            for (int fn2 = 0; fn2 < 2; fn2++) {
                uint32_t addr = b_base +
                    (uint32_t)(((stg * BN) + b_row + fn2 * 16) * LDSH + kk + b_csel) * 2;
                uint32_t r0, r1, r2, r3;
                ldm_x4(r0, r1, r2, r3, addr);
                bfr[fn2 * 2][0] = r0;     bfr[fn2 * 2][1] = r1;
                bfr[fn2 * 2 + 1][0] = r2; bfr[fn2 * 2 + 1][1] = r3;
            }
#pragma unroll
            for (int fm = 0; fm < 4; fm++)
#pragma unroll
                for (int fn = 0; fn < 4; fn++)
                    mma_fp16(acc[fm][fn], afr[fm], bfr[fn]);
        }
    }

    // epilogue
#pragma unroll
    for (int fm = 0; fm < 4; fm++) {
        int r0 = rowbase + wm + fm * 16 + g;
#pragma unroll
        for (int fn = 0; fn < 4; fn++) {
            int col = colbase + wn + fn * 8 + 2 * tg;
            if constexpr (MODE == 1) {
                // wsrc = bias
                float2 bb = *reinterpret_cast<const float2*>(wsrc + col);
                float2 v0 = make_float2(acc[fm][fn][0] + bb.x, acc[fm][fn][1] + bb.y);
                float2 v1 = make_float2(acc[fm][fn][2] + bb.x, acc[fm][fn][3] + bb.y);
                *reinterpret_cast<float2*>(&Cout[(size_t)r0 * NOUT + col]) = v0;
                *reinterpret_cast<float2*>(&Cout[(size_t)(r0 + 8) * NOUT + col]) = v1;
            } else {
                // wsrc = qkv_w (f32); add delta in f32, round once to fp16
                int e0 = (blockIdx.z ? 2 * DD : 0) + r0;
                float2 w0 = *reinterpret_cast<const float2*>(&wsrc[(size_t)e0 * DD + col]);
                float2 w1 = *reinterpret_cast<const float2*>(&wsrc[(size_t)(e0 + 8) * DD + col]);
                __half2 h0 = __floats2half2_rn(acc[fm][fn][0] + w0.x, acc[fm][fn][1] + w0.y);
                __half2 h1 = __floats2half2_rn(acc[fm][fn][2] + w1.x, acc[fm][fn][3] + w1.y);
                *reinterpret_cast<__half2*>(&g_wt[(size_t)e0 * DD + col]) = h0;
                *reinterpret_cast<__half2*>(&g_wt[(size_t)(e0 + 8) * DD + col]) = h1;
            }
        }
    }
}

// ---------------- launch ----------------
extern "C" void kernel_launch(void* const* d_in, const int* in_sizes, int n_in,
                              void* d_out, int out_size) {
    const float* x     = (const float*)d_in[0];
    const float* qkv_w = (const float*)d_in[1];
    const float* qkv_b = (const float*)d_in[2];
    const float* la_q  = (const float*)d_in[3];
    const float* lb_q  = (const float*)d_in[4];
    const float* la_v  = (const float*)d_in[5];
    const float* lb_v  = (const float*)d_in[6];
    const float* A_q   = (const float*)d_in[7];
    const float* B_q   = (const float*)d_in[8];
    const float* A_v   = (const float*)d_in[9];
    const float* B_v   = (const float*)d_in[10];
    const float* gate  = (const float*)d_in[11];
    const float* alpha = (const float*)d_in[12];

    const int SMEM = NS * (BM + BN) * LDSH * (int)sizeof(__half);  // 110592
    cudaFuncSetAttribute((const void*)gemm_fp16<0>,
                         cudaFuncAttributeMaxDynamicSharedMemorySize, SMEM);
    cudaFuncSetAttribute((const void*)gemm_fp16<1>,
                         cudaFuncAttributeMaxDynamicSharedMemorySize, SMEM);

    // Fused prepass: x convert (768 blk) | w-mid convert (72 blk) | norms (32 blk)
    prep_kernel<<<872, 256>>>((const float4*)x,
                              (const float4*)(qkv_w + (size_t)DD * DD),
                              A_q, B_q, A_v, B_v);

    build_kernel<<<144, 256>>>(A_q, la_q, A_v, la_v, B_q, lb_q, B_v, lb_v, gate, alpha);

    // Fold low-rank into weights: W'[q rows, v rows] = W + B_s @ A^T  (writes g_wt q/v thirds)
    gemm_fp16<0><<<dim3(6, 6, 2), 256, SMEM>>>(qkv_w, nullptr);

    // Main GEMM: out = xt @ wt^T + bias  (uniform K=768)
    gemm_fp16<1><<<dim3(18, 64, 1), 256, SMEM>>>(qkv_b, (float*)d_out);
}